// round 1
// baseline (speedup 1.0000x reference)
#include <cuda_runtime.h>

#define NQ      4
#define DIM     16      // 2^NQ
#define NHEADS  8
#define NLAYERS 2
#define EMBED   32
#define NBASIS  81      // 3^4 basis terms {1,cos,sin}^4

// Per-head polynomial coefficients: C[h][k] is a float4 holding the 4 Z-expval
// coefficients for basis term k (k = k0*27 + k1*9 + k2*3 + k3).
__device__ float4 g_C[NHEADS * NBASIS];

// ---------------------------------------------------------------------------
// Precompute: per head, build U (fixed circuit), A_i = Re(U^H Z_i U), then
// project onto the {1, cos, sin}^4 basis. Grid = 8 blocks (1/head), 256 thr.
// ---------------------------------------------------------------------------
__global__ void qmha_precompute(const float* __restrict__ params) {
    __shared__ float Ur[DIM][DIM];   // [column p][state s]
    __shared__ float Ui[DIM][DIM];
    __shared__ float A[NQ][DIM * DIM];

    const int h   = blockIdx.x;
    const int tid = threadIdx.x;

    // --- Step 1: 16 threads simulate the 16 basis columns of U_h ---
    if (tid < DIM) {
        float re[DIM], im[DIM];
        #pragma unroll
        for (int s = 0; s < DIM; s++) { re[s] = 0.f; im[s] = 0.f; }
        re[tid] = 1.f;

        const float* ph = params + h * NLAYERS * NQ * 3;

        #pragma unroll
        for (int l = 0; l < NLAYERS; l++) {
            #pragma unroll
            for (int w = 0; w < NQ; w++) {
                const int mask = 1 << (3 - w);   // qubit w -> bit (3-w)
                float tx = ph[(l * NQ + w) * 3 + 0];
                float ty = ph[(l * NQ + w) * 3 + 1];
                float tz = ph[(l * NQ + w) * 3 + 2];
                float cx = cosf(0.5f * tx), sx = sinf(0.5f * tx);
                float cy = cosf(0.5f * ty), sy = sinf(0.5f * ty);
                float cz = cosf(0.5f * tz), sz = sinf(0.5f * tz);
                #pragma unroll
                for (int s0 = 0; s0 < DIM; s0++) {
                    if (s0 & mask) continue;
                    const int s1 = s0 | mask;
                    float r0 = re[s0], i0 = im[s0], r1 = re[s1], i1 = im[s1];
                    // RX(tx): [[c, -i s],[-i s, c]]
                    float nr0 = cx * r0 + sx * i1;
                    float ni0 = cx * i0 - sx * r1;
                    float nr1 = sx * i0 + cx * r1;
                    float ni1 = -sx * r0 + cx * i1;
                    // RY(ty): [[c,-s],[s,c]]
                    r0 = nr0; i0 = ni0; r1 = nr1; i1 = ni1;
                    nr0 = cy * r0 - sy * r1;
                    ni0 = cy * i0 - sy * i1;
                    nr1 = sy * r0 + cy * r1;
                    ni1 = sy * i0 + cy * i1;
                    // RZ(tz): diag(e^{-i t/2}, e^{+i t/2})
                    r0 = nr0; i0 = ni0; r1 = nr1; i1 = ni1;
                    re[s0] = cz * r0 + sz * i0;
                    im[s0] = cz * i0 - sz * r0;
                    re[s1] = cz * r1 - sz * i1;
                    im[s1] = cz * i1 + sz * r1;
                }
            }
            // CNOT ring: (0,1),(1,2),(2,3),(3,0)
            #pragma unroll
            for (int e = 0; e < NQ; e++) {
                const int c = e, t = (e + 1) & 3;
                const int cm = 1 << (3 - c), tm = 1 << (3 - t);
                #pragma unroll
                for (int s = 0; s < DIM; s++) {
                    if ((s & cm) && !(s & tm)) {
                        const int s2 = s | tm;
                        float tr = re[s]; re[s] = re[s2]; re[s2] = tr;
                        float ti = im[s]; im[s] = im[s2]; im[s2] = ti;
                    }
                }
            }
        }
        #pragma unroll
        for (int s = 0; s < DIM; s++) { Ur[tid][s] = re[s]; Ui[tid][s] = im[s]; }
    }
    __syncthreads();

    // --- Step 2: A_i[p][q] = sum_s z_i(s) Re(conj(U[s,p]) U[s,q]) ---
    {
        const int p = tid >> 4, q = tid & 15;
        float a0 = 0.f, a1 = 0.f, a2 = 0.f, a3 = 0.f;
        #pragma unroll
        for (int s = 0; s < DIM; s++) {
            float rr = Ur[p][s] * Ur[q][s] + Ui[p][s] * Ui[q][s];
            a0 += (s & 8) ? -rr : rr;   // qubit 0 -> bit 3
            a1 += (s & 4) ? -rr : rr;
            a2 += (s & 2) ? -rr : rr;
            a3 += (s & 1) ? -rr : rr;
        }
        A[0][tid] = a0; A[1][tid] = a1; A[2][tid] = a2; A[3][tid] = a3;
    }
    __syncthreads();

    // --- Step 3: project onto {1, cos, sin}^4 basis ---
    // per-qubit map of (a,b) pair products of cos(x/2)/sin(x/2):
    //   (0,0)->0.5*1 + 0.5*cos ; (1,1)->0.5*1 - 0.5*cos ; (0,1),(1,0)->0.5*sin
    if (tid < NBASIS) {
        int kw0 = tid / 27, kw1 = (tid / 9) % 3, kw2 = (tid / 3) % 3, kw3 = tid % 3;
        int kw[4] = {kw0, kw1, kw2, kw3};
        float acc0 = 0.f, acc1 = 0.f, acc2 = 0.f, acc3 = 0.f;
        #pragma unroll
        for (int m = 0; m < 16; m++) {
            int p = 0, q = 0;
            float wgt = 1.0f / 16.0f;
            #pragma unroll
            for (int w = 0; w < 4; w++) {
                const int opt = (m >> w) & 1;
                const int k = kw[w];
                int a, b;
                if (k == 0)      { a = opt; b = opt; }
                else if (k == 1) { a = opt; b = opt; if (opt) wgt = -wgt; }
                else             { a = opt; b = 1 - opt; }
                p |= a << (3 - w);
                q |= b << (3 - w);
            }
            acc0 += wgt * A[0][p * 16 + q];
            acc1 += wgt * A[1][p * 16 + q];
            acc2 += wgt * A[2][p * 16 + q];
            acc3 += wgt * A[3][p * 16 + q];
        }
        g_C[h * NBASIS + tid] = make_float4(acc0, acc1, acc2, acc3);
    }
}

// ---------------------------------------------------------------------------
// Main: one thread per token. Evaluate 8 head polynomials + fused output GEMM.
// ---------------------------------------------------------------------------
__global__ __launch_bounds__(256) void qmha_main(
    const float4* __restrict__ x,    // [tokens][8] float4 (EMBED=32)
    const float*  __restrict__ W,    // [EMBED][32] row-major (W_out)
    const float*  __restrict__ b,    // [EMBED]
    float4*       __restrict__ out,  // [tokens][8] float4
    int tokens)
{
    __shared__ float4 Cs[NHEADS * NBASIS];   // 10368 B
    __shared__ float  Wt[32][32];            // Wt[j][e] = W[e][j]
    __shared__ float  bs[32];

    const int tid = threadIdx.x;
    for (int i = tid; i < NHEADS * NBASIS; i += 256) Cs[i] = g_C[i];
    for (int i = tid; i < 1024; i += 256) {
        const int e = i >> 5, j = i & 31;
        Wt[j][e] = W[i];
    }
    if (tid < 32) bs[tid] = b[tid];
    __syncthreads();

    const int tok = blockIdx.x * 256 + tid;
    if (tok >= tokens) return;

    float4 xv[8];
    #pragma unroll
    for (int h = 0; h < 8; h++) xv[h] = x[tok * 8 + h];

    float outr[32];
    #pragma unroll
    for (int e = 0; e < 32; e++) outr[e] = bs[e];

    for (int h = 0; h < 8; h++) {
        float c0, s0, c1, s1, c2, s2, c3, s3;
        __sincosf(xv[h].x, &s0, &c0);
        __sincosf(xv[h].y, &s1, &c1);
        __sincosf(xv[h].z, &s2, &c2);
        __sincosf(xv[h].w, &s3, &c3);

        const float A9[9] = {1.f, c1, s1, c0, c0 * c1, c0 * s1, s0, s0 * c1, s0 * s1};
        const float B9[9] = {1.f, c3, s3, c2, c2 * c3, c2 * s3, s2, s2 * c3, s2 * s3};

        float4 acc = make_float4(0.f, 0.f, 0.f, 0.f);
        const float4* Ch = &Cs[h * NBASIS];
        #pragma unroll
        for (int i = 0; i < 9; i++) {
            float4 part = make_float4(0.f, 0.f, 0.f, 0.f);
            #pragma unroll
            for (int j = 0; j < 9; j++) {
                const float4 C = Ch[i * 9 + j];
                const float t = B9[j];
                part.x += C.x * t;
                part.y += C.y * t;
                part.z += C.z * t;
                part.w += C.w * t;
            }
            const float a = A9[i];
            acc.x += a * part.x;
            acc.y += a * part.y;
            acc.z += a * part.z;
            acc.w += a * part.w;
        }

        // fold ev into output via W (Wt[j][e] broadcast from smem)
        const int jb = h * 4;
        #pragma unroll
        for (int q = 0; q < 4; q++) {
            const float ev = (q == 0) ? acc.x : (q == 1) ? acc.y : (q == 2) ? acc.z : acc.w;
            const float* wrow = &Wt[jb + q][0];
            #pragma unroll
            for (int e = 0; e < 32; e++) outr[e] += ev * wrow[e];
        }
    }

    #pragma unroll
    for (int v = 0; v < 8; v++) {
        out[tok * 8 + v] = make_float4(outr[4 * v + 0], outr[4 * v + 1],
                                       outr[4 * v + 2], outr[4 * v + 3]);
    }
}

extern "C" void kernel_launch(void* const* d_in, const int* in_sizes, int n_in,
                              void* d_out, int out_size) {
    const float* x      = (const float*)d_in[0];
    const float* params = (const float*)d_in[1];
    const float* W      = (const float*)d_in[2];
    const float* b      = (const float*)d_in[3];

    const int tokens = in_sizes[0] / EMBED;   // B*S = 131072

    qmha_precompute<<<NHEADS, 256>>>(params);

    const int threads = 256;
    const int blocks = (tokens + threads - 1) / threads;
    qmha_main<<<blocks, threads>>>((const float4*)x, W, b, (float4*)d_out, tokens);
}

// round 2
// speedup vs baseline: 1.2381x; 1.2381x over previous
#include <cuda_runtime.h>

#define NQ      4
#define DIM     16      // 2^NQ
#define NHEADS  8
#define NLAYERS 2
#define EMBED   32
#define NBASIS  81      // 3^4 basis terms {1,cos,sin}^4

// ---------------------------------------------------------------------------
// All warp-uniform read-only data lives in __constant__ memory so the main
// kernel's coefficient stream uses LDCU/UR (uniform-const port) instead of
// hammering L1TEX with broadcast LDS (the round-1 bottleneck: L1=67%).
// ---------------------------------------------------------------------------
struct ConstData {
    float4 C[NHEADS * NBASIS];   // per-head polynomial coeffs (4 Z-outputs packed)
    float4 Wt4[32][8];           // Wt4[j][e4].k = W_out[e4*4+k][j]
    float4 b4[8];                // bias packed
};

__constant__ ConstData cC;
__device__   ConstData g_stage;   // written by precompute, copied to cC

// ---------------------------------------------------------------------------
// Precompute: per head, build U (fixed circuit), A_i = Re(U^H Z_i U), then
// project onto the {1, cos, sin}^4 basis. Grid = 8 blocks (1/head), 256 thr.
// Block 0 additionally packs Wt4 and b4.
// ---------------------------------------------------------------------------
__global__ void qmha_precompute(const float* __restrict__ params,
                                const float* __restrict__ W,
                                const float* __restrict__ b) {
    __shared__ float Ur[DIM][DIM];   // [column p][state s]
    __shared__ float Ui[DIM][DIM];
    __shared__ float A[NQ][DIM * DIM];

    const int h   = blockIdx.x;
    const int tid = threadIdx.x;

    // --- Step 1: 16 threads simulate the 16 basis columns of U_h ---
    if (tid < DIM) {
        float re[DIM], im[DIM];
        #pragma unroll
        for (int s = 0; s < DIM; s++) { re[s] = 0.f; im[s] = 0.f; }
        re[tid] = 1.f;

        const float* ph = params + h * NLAYERS * NQ * 3;

        #pragma unroll
        for (int l = 0; l < NLAYERS; l++) {
            #pragma unroll
            for (int w = 0; w < NQ; w++) {
                const int mask = 1 << (3 - w);   // qubit w -> bit (3-w)
                float tx = ph[(l * NQ + w) * 3 + 0];
                float ty = ph[(l * NQ + w) * 3 + 1];
                float tz = ph[(l * NQ + w) * 3 + 2];
                float cx = cosf(0.5f * tx), sx = sinf(0.5f * tx);
                float cy = cosf(0.5f * ty), sy = sinf(0.5f * ty);
                float cz = cosf(0.5f * tz), sz = sinf(0.5f * tz);
                #pragma unroll
                for (int s0 = 0; s0 < DIM; s0++) {
                    if (s0 & mask) continue;
                    const int s1 = s0 | mask;
                    float r0 = re[s0], i0 = im[s0], r1 = re[s1], i1 = im[s1];
                    // RX(tx)
                    float nr0 = cx * r0 + sx * i1;
                    float ni0 = cx * i0 - sx * r1;
                    float nr1 = sx * i0 + cx * r1;
                    float ni1 = -sx * r0 + cx * i1;
                    // RY(ty)
                    r0 = nr0; i0 = ni0; r1 = nr1; i1 = ni1;
                    nr0 = cy * r0 - sy * r1;
                    ni0 = cy * i0 - sy * i1;
                    nr1 = sy * r0 + cy * r1;
                    ni1 = sy * i0 + cy * i1;
                    // RZ(tz)
                    r0 = nr0; i0 = ni0; r1 = nr1; i1 = ni1;
                    re[s0] = cz * r0 + sz * i0;
                    im[s0] = cz * i0 - sz * r0;
                    re[s1] = cz * r1 - sz * i1;
                    im[s1] = cz * i1 + sz * r1;
                }
            }
            // CNOT ring: (0,1),(1,2),(2,3),(3,0)
            #pragma unroll
            for (int e = 0; e < NQ; e++) {
                const int c = e, t = (e + 1) & 3;
                const int cm = 1 << (3 - c), tm = 1 << (3 - t);
                #pragma unroll
                for (int s = 0; s < DIM; s++) {
                    if ((s & cm) && !(s & tm)) {
                        const int s2 = s | tm;
                        float tr = re[s]; re[s] = re[s2]; re[s2] = tr;
                        float ti = im[s]; im[s] = im[s2]; im[s2] = ti;
                    }
                }
            }
        }
        #pragma unroll
        for (int s = 0; s < DIM; s++) { Ur[tid][s] = re[s]; Ui[tid][s] = im[s]; }
    }
    __syncthreads();

    // --- Step 2: A_i[p][q] = sum_s z_i(s) Re(conj(U[s,p]) U[s,q]) ---
    {
        const int p = tid >> 4, q = tid & 15;
        float a0 = 0.f, a1 = 0.f, a2 = 0.f, a3 = 0.f;
        #pragma unroll
        for (int s = 0; s < DIM; s++) {
            float rr = Ur[p][s] * Ur[q][s] + Ui[p][s] * Ui[q][s];
            a0 += (s & 8) ? -rr : rr;
            a1 += (s & 4) ? -rr : rr;
            a2 += (s & 2) ? -rr : rr;
            a3 += (s & 1) ? -rr : rr;
        }
        A[0][tid] = a0; A[1][tid] = a1; A[2][tid] = a2; A[3][tid] = a3;
    }
    __syncthreads();

    // --- Step 3: project onto {1, cos, sin}^4 basis ---
    if (tid < NBASIS) {
        int kw0 = tid / 27, kw1 = (tid / 9) % 3, kw2 = (tid / 3) % 3, kw3 = tid % 3;
        int kw[4] = {kw0, kw1, kw2, kw3};
        float acc0 = 0.f, acc1 = 0.f, acc2 = 0.f, acc3 = 0.f;
        #pragma unroll
        for (int m = 0; m < 16; m++) {
            int p = 0, q = 0;
            float wgt = 1.0f / 16.0f;
            #pragma unroll
            for (int w = 0; w < 4; w++) {
                const int opt = (m >> w) & 1;
                const int k = kw[w];
                int a, bb;
                if (k == 0)      { a = opt; bb = opt; }
                else if (k == 1) { a = opt; bb = opt; if (opt) wgt = -wgt; }
                else             { a = opt; bb = 1 - opt; }
                p |= a << (3 - w);
                q |= bb << (3 - w);
            }
            acc0 += wgt * A[0][p * 16 + q];
            acc1 += wgt * A[1][p * 16 + q];
            acc2 += wgt * A[2][p * 16 + q];
            acc3 += wgt * A[3][p * 16 + q];
        }
        g_stage.C[h * NBASIS + tid] = make_float4(acc0, acc1, acc2, acc3);
    }

    // --- Block 0: pack Wt4[j][e4] (transposed W_out) and b4 ---
    if (h == 0) {
        for (int i = tid; i < EMBED * 32; i += blockDim.x) {
            const int e = i >> 5, j = i & 31;          // W[e][j]
            ((float*)&g_stage.Wt4[j][0])[e] = W[i];    // Wt4[j][e/4].comp(e%4)
        }
        if (tid < EMBED) ((float*)g_stage.b4)[tid] = b[tid];
    }
}

// ---------------------------------------------------------------------------
// Main: one thread per token. All coefficients from __constant__ (LDCU path).
// ---------------------------------------------------------------------------
__global__ __launch_bounds__(256) void qmha_main(
    const float4* __restrict__ x,    // [tokens][8] float4 (EMBED=32)
    float4*       __restrict__ out,  // [tokens][8] float4
    int tokens)
{
    const int tok = blockIdx.x * 256 + threadIdx.x;
    if (tok >= tokens) return;

    float4 outr4[8];
    #pragma unroll
    for (int e4 = 0; e4 < 8; e4++) outr4[e4] = cC.b4[e4];

    for (int h = 0; h < NHEADS; h++) {
        // token's 8 float4s share one 128B line: first load pulls it, rest hit L1
        const float4 xvh = x[tok * 8 + h];

        float c0, s0, c1, s1, c2, s2, c3, s3;
        __sincosf(xvh.x, &s0, &c0);
        __sincosf(xvh.y, &s1, &c1);
        __sincosf(xvh.z, &s2, &c2);
        __sincosf(xvh.w, &s3, &c3);

        const float A9[9] = {1.f, c1, s1, c0, c0 * c1, c0 * s1, s0, s0 * c1, s0 * s1};
        const float B9[9] = {1.f, c3, s3, c2, c2 * c3, c2 * s3, s2, s2 * c3, s2 * s3};

        float4 acc = make_float4(0.f, 0.f, 0.f, 0.f);
        #pragma unroll
        for (int i = 0; i < 9; i++) {
            float4 part = make_float4(0.f, 0.f, 0.f, 0.f);
            #pragma unroll
            for (int j = 0; j < 9; j++) {
                const float4 Cv = cC.C[h * NBASIS + i * 9 + j];   // ld.const.v4
                const float t = B9[j];
                part.x += Cv.x * t;
                part.y += Cv.y * t;
                part.z += Cv.z * t;
                part.w += Cv.w * t;
            }
            const float a = A9[i];
            acc.x += a * part.x;
            acc.y += a * part.y;
            acc.z += a * part.z;
            acc.w += a * part.w;
        }

        // fold the 4 expvals into the 32 outputs via constant Wt4
        #pragma unroll
        for (int q = 0; q < 4; q++) {
            const float ev = (q == 0) ? acc.x : (q == 1) ? acc.y
                            : (q == 2) ? acc.z : acc.w;
            #pragma unroll
            for (int e4 = 0; e4 < 8; e4++) {
                const float4 w = cC.Wt4[h * 4 + q][e4];           // ld.const.v4
                outr4[e4].x += ev * w.x;
                outr4[e4].y += ev * w.y;
                outr4[e4].z += ev * w.z;
                outr4[e4].w += ev * w.w;
            }
        }
    }

    #pragma unroll
    for (int e4 = 0; e4 < 8; e4++) out[tok * 8 + e4] = outr4[e4];
}

extern "C" void kernel_launch(void* const* d_in, const int* in_sizes, int n_in,
                              void* d_out, int out_size) {
    const float* x      = (const float*)d_in[0];
    const float* params = (const float*)d_in[1];
    const float* W      = (const float*)d_in[2];
    const float* b      = (const float*)d_in[3];

    const int tokens = in_sizes[0] / EMBED;   // B*S = 131072

    qmha_precompute<<<NHEADS, 256>>>(params, W, b);

    void* stage_ptr = nullptr;
    cudaGetSymbolAddress(&stage_ptr, g_stage);
    cudaMemcpyToSymbolAsync(cC, stage_ptr, sizeof(ConstData), 0,
                            cudaMemcpyDeviceToDevice, 0);

    const int threads = 256;
    const int blocks = (tokens + threads - 1) / threads;
    qmha_main<<<blocks, threads>>>((const float4*)x, (float4*)d_out, tokens);
}